// round 1
// baseline (speedup 1.0000x reference)
#include <cuda_runtime.h>
#include <cuda_bf16.h>
#include <math.h>

// Problem constants
#define Sq    2048
#define HIDN  2048
#define NH    16
#define NKH   8
#define HD    128
#define GRP   2          // NH / NKH
#define EPSV  1e-6f
#define SCALEV 0.08838834764831845f   // 128^-0.5
#define NEGV  (-1000000000.0f)

// ---------------- static device scratch (allocation-free rule) ----------------
__device__ float g_q[Sq * NH * HD];          // 2048 x 2048
__device__ float g_k[Sq * NKH * HD];         // 2048 x 1024
__device__ float g_v[Sq * NKH * HD];         // 2048 x 1024
__device__ float g_scores[(size_t)NH * Sq * Sq];  // 16 x 2048 x 2048 (256MB)
__device__ float g_y[Sq * NH * HD];          // 2048 x 2048

// ---------------- generic tiled SGEMM ----------------
// C[M,N] = A[M,K] * op(B)
//   TB = true : B is N x K row-major (ldb), C[m,n] = sum_k A[m,k]*B[n,k]
//   TB = false: B is K x N row-major (ldb), C[m,n] = sum_k A[m,k]*B[k,n]
// Requires M,N multiples of 64 and K multiple of 16 (all shapes here comply).
template <bool TB>
__global__ void gemm_kernel(const float* __restrict__ A,
                            const float* __restrict__ B,
                            float* __restrict__ C,
                            int M, int N, int K,
                            int lda, int ldb, int ldc)
{
    __shared__ float As[16][65];   // As[k][m]
    __shared__ float Bs[16][65];   // Bs[k][n]

    const int tid = threadIdx.x;          // 256 threads
    const int tx = tid & 15;              // 0..15 (n dir)
    const int ty = tid >> 4;              // 0..15 (m dir)
    const int bm = blockIdx.y * 64;
    const int bn = blockIdx.x * 64;

    float acc[4][4];
    #pragma unroll
    for (int i = 0; i < 4; i++)
        #pragma unroll
        for (int j = 0; j < 4; j++)
            acc[i][j] = 0.0f;

    for (int k0 = 0; k0 < K; k0 += 16) {
        // Load A tile (64 rows x 16 k) : 1024 elems, 4 per thread
        #pragma unroll
        for (int i = 0; i < 4; i++) {
            int e = tid * 4 + i;
            int m = e >> 4, kk = e & 15;
            As[kk][m] = A[(size_t)(bm + m) * lda + (k0 + kk)];
        }
        if (TB) {
            #pragma unroll
            for (int i = 0; i < 4; i++) {
                int e = tid * 4 + i;
                int n = e >> 4, kk = e & 15;
                Bs[kk][n] = B[(size_t)(bn + n) * ldb + (k0 + kk)];
            }
        } else {
            #pragma unroll
            for (int i = 0; i < 4; i++) {
                int e = tid * 4 + i;
                int kk = e >> 6, n = e & 63;
                Bs[kk][n] = B[(size_t)(k0 + kk) * ldb + (bn + n)];
            }
        }
        __syncthreads();

        #pragma unroll
        for (int kk = 0; kk < 16; kk++) {
            float a[4], b[4];
            #pragma unroll
            for (int i = 0; i < 4; i++) a[i] = As[kk][ty * 4 + i];
            #pragma unroll
            for (int j = 0; j < 4; j++) b[j] = Bs[kk][tx * 4 + j];
            #pragma unroll
            for (int i = 0; i < 4; i++)
                #pragma unroll
                for (int j = 0; j < 4; j++)
                    acc[i][j] += a[i] * b[j];
        }
        __syncthreads();
    }

    #pragma unroll
    for (int i = 0; i < 4; i++)
        #pragma unroll
        for (int j = 0; j < 4; j++)
            C[(size_t)(bm + ty * 4 + i) * ldc + (bn + tx * 4 + j)] = acc[i][j];
}

// ---------------- RMSNorm + RoPE (in place) ----------------
// grid = (S, nheads), block = 128 (one thread per d)
__global__ void norm_rope_kernel(float* __restrict__ x,
                                 const float* __restrict__ w,
                                 const float* __restrict__ pcos,
                                 const float* __restrict__ psin,
                                 int rowstride)
{
    const int s = blockIdx.x;
    const int h = blockIdx.y;
    const int d = threadIdx.x;   // 0..127

    float* row = x + (size_t)s * rowstride + h * HD;
    float v = row[d];

    __shared__ float red[128];
    __shared__ float xsh[128];

    red[d] = v * v;
    __syncthreads();
    #pragma unroll
    for (int off = 64; off > 0; off >>= 1) {
        if (d < off) red[d] += red[d + off];
        __syncthreads();
    }
    float r = rsqrtf(red[0] * (1.0f / HD) + EPSV);
    float xn = v * r * w[d];
    xsh[d] = xn;
    __syncthreads();

    float c  = pcos[s * 64 + (d & 63)];
    float sn = psin[s * 64 + (d & 63)];
    float out;
    if (d < 64) out = xsh[d] * c - xsh[d + 64] * sn;
    else        out = xsh[d - 64] * sn + xsh[d] * c;
    row[d] = out;
}

// ---------------- softmax (scale + causal mask fused) ----------------
// one block per (head,row). row length = S = 2048, 256 threads x 8 elems
__global__ void softmax_kernel(float* __restrict__ scores)
{
    const int row = blockIdx.x;        // h*S + i
    const int i = row & (Sq - 1);
    float* p = scores + (size_t)row * Sq;
    const int t = threadIdx.x;

    float vals[8];
    float vmax = -INFINITY;
    #pragma unroll
    for (int j0 = 0; j0 < 8; j0++) {
        int j = t + j0 * 256;
        float v = p[j] * SCALEV + (j <= i ? 0.0f : NEGV);
        vals[j0] = v;
        vmax = fmaxf(vmax, v);
    }

    __shared__ float sh[256];
    sh[t] = vmax;
    __syncthreads();
    #pragma unroll
    for (int off = 128; off > 0; off >>= 1) {
        if (t < off) sh[t] = fmaxf(sh[t], sh[t + off]);
        __syncthreads();
    }
    vmax = sh[0];
    __syncthreads();

    float sum = 0.0f;
    #pragma unroll
    for (int j0 = 0; j0 < 8; j0++) {
        vals[j0] = __expf(vals[j0] - vmax);
        sum += vals[j0];
    }
    sh[t] = sum;
    __syncthreads();
    #pragma unroll
    for (int off = 128; off > 0; off >>= 1) {
        if (t < off) sh[t] += sh[t + off];
        __syncthreads();
    }
    float inv = 1.0f / sh[0];
    #pragma unroll
    for (int j0 = 0; j0 < 8; j0++)
        p[t + j0 * 256] = vals[j0] * inv;
}

// ---------------- k_new / v_new tail copy ----------------
__global__ void tail_copy_kernel(const float* __restrict__ k,
                                 const float* __restrict__ v,
                                 float* __restrict__ out)
{
    int t = blockIdx.x * blockDim.x + threadIdx.x;   // 0..2047
    const size_t base = (size_t)Sq * HIDN;           // after y
    if (t < NKH * HD)
        out[base + t] = k[(size_t)(Sq - 1) * (NKH * HD) + t];
    else
        out[base + t] = v[(size_t)(Sq - 1) * (NKH * HD) + (t - NKH * HD)];
}

// ---------------- launcher ----------------
extern "C" void kernel_launch(void* const* d_in, const int* in_sizes, int n_in,
                              void* d_out, int out_size)
{
    const float* hs   = (const float*)d_in[0];
    const float* pcos = (const float*)d_in[1];
    const float* psin = (const float*)d_in[2];
    // d_in[3] = atten_mask (causal, reproduced arithmetically)
    const float* Wq   = (const float*)d_in[4];
    const float* Wk   = (const float*)d_in[5];
    const float* Wv   = (const float*)d_in[6];
    const float* Wo   = (const float*)d_in[7];
    const float* qw   = (const float*)d_in[8];
    const float* kw   = (const float*)d_in[9];
    float* out = (float*)d_out;

    float *q, *k, *v, *sc, *y;
    cudaGetSymbolAddress((void**)&q,  g_q);
    cudaGetSymbolAddress((void**)&k,  g_k);
    cudaGetSymbolAddress((void**)&v,  g_v);
    cudaGetSymbolAddress((void**)&sc, g_scores);
    cudaGetSymbolAddress((void**)&y,  g_y);

    dim3 blk(256);

    // ---- QKV projections: X(2048x2048) @ W^T ----
    gemm_kernel<true><<<dim3(HIDN/64, Sq/64), blk>>>(hs, Wq, q, Sq, NH*HD,  HIDN, HIDN, HIDN, NH*HD);
    gemm_kernel<true><<<dim3((NKH*HD)/64, Sq/64), blk>>>(hs, Wk, k, Sq, NKH*HD, HIDN, HIDN, HIDN, NKH*HD);
    gemm_kernel<true><<<dim3((NKH*HD)/64, Sq/64), blk>>>(hs, Wv, v, Sq, NKH*HD, HIDN, HIDN, HIDN, NKH*HD);

    // ---- RMSNorm + RoPE ----
    norm_rope_kernel<<<dim3(Sq, NH),  128>>>(q, qw, pcos, psin, NH * HD);
    norm_rope_kernel<<<dim3(Sq, NKH), 128>>>(k, kw, pcos, psin, NKH * HD);

    // ---- scores: per head, Q_h(2048x128) @ K_kh^T(128x2048) ----
    for (int h = 0; h < NH; h++) {
        const float* Ah = q + h * HD;
        const float* Bh = k + (h / GRP) * HD;
        float* Ch = sc + (size_t)h * Sq * Sq;
        gemm_kernel<true><<<dim3(Sq/64, Sq/64), blk>>>(Ah, Bh, Ch, Sq, Sq, HD, NH*HD, NKH*HD, Sq);
    }

    // ---- softmax with scale + causal mask ----
    softmax_kernel<<<NH * Sq, 256>>>(sc);

    // ---- AV: per head, P_h(2048x2048) @ V_kh(2048x128) -> y[:, h*128:...] ----
    for (int h = 0; h < NH; h++) {
        const float* Ah = sc + (size_t)h * Sq * Sq;
        const float* Bh = v + (h / GRP) * HD;
        float* Ch = y + h * HD;
        gemm_kernel<false><<<dim3(HD/64, Sq/64), blk>>>(Ah, Bh, Ch, Sq, HD, Sq, Sq, NKH*HD, NH*HD);
    }

    // ---- output projection: Y(2048x2048) @ Wo^T ----
    gemm_kernel<true><<<dim3(HIDN/64, Sq/64), blk>>>(y, Wo, out, Sq, HIDN, HIDN, NH*HD, HIDN, HIDN);

    // ---- k_new / v_new ----
    tail_copy_kernel<<<8, 256>>>(k, v, out);
}

// round 2
// speedup vs baseline: 7.9466x; 7.9466x over previous
#include <cuda_runtime.h>
#include <cuda_bf16.h>
#include <math.h>

// Problem constants
#define Sq    2048
#define HIDN  2048
#define NH    16
#define NKH   8
#define HD    128
#define GRP   2          // NH / NKH
#define EPSV  1e-6f
#define SCALEV 0.08838834764831845f   // 128^-0.5
#define NEGV  (-1000000000.0f)

// ---------------- static device scratch (allocation-free rule) ----------------
__device__ float g_q[Sq * NH * HD];               // 2048 x 2048
__device__ float g_k[Sq * NKH * HD];              // 2048 x 1024
__device__ float g_v[Sq * NKH * HD];              // 2048 x 1024
__device__ float g_scores[(size_t)NH * Sq * Sq];  // 16 x 2048 x 2048
__device__ float g_y[Sq * NH * HD];               // 2048 x 2048

// ---------------- tf32 helpers ----------------
__device__ __forceinline__ unsigned f2tf32(float f) {
    unsigned u;
    asm("cvt.rna.tf32.f32 %0, %1;" : "=r"(u) : "f"(f));
    return u;
}

__device__ __forceinline__ void mma_tf32(float c[4],
                                         unsigned a0, unsigned a1, unsigned a2, unsigned a3,
                                         unsigned b0, unsigned b1)
{
    asm volatile(
        "mma.sync.aligned.m16n8k8.row.col.f32.tf32.tf32.f32 "
        "{%0,%1,%2,%3}, {%4,%5,%6,%7}, {%8,%9}, {%0,%1,%2,%3};"
        : "+f"(c[0]), "+f"(c[1]), "+f"(c[2]), "+f"(c[3])
        : "r"(a0), "r"(a1), "r"(a2), "r"(a3), "r"(b0), "r"(b1));
}

// ---------------- tf32 tensor-core GEMM ----------------
// C[M,N] = A[M,K] * op(B), fp32 in/out, tf32 MMA accumulate-fp32.
//   TB=true : B is N x K row-major ; TB=false: B is K x N row-major.
// Batched over blockIdx.z with element strides sA/sB/sC; B batch index = z / bdiv.
// CAUSAL_SKIP: skip block if its n-range is entirely > its m-range (square tiles).
// CAUSAL_K   : K-loop clamped to bm+BM (A is strictly-lower-triangular-ish).
// Requires: M % 128 == 0, N % 128 == 0, K % 32 == 0, 16B-aligned rows.
template <bool TB, bool CAUSAL_SKIP, bool CAUSAL_K>
__global__ __launch_bounds__(256)
void mma_gemm(const float* __restrict__ A,
              const float* __restrict__ B,
              float* __restrict__ C,
              int M, int N, int K,
              int lda, int ldb, int ldc,
              long sA, long sB, long sC, int bdiv)
{
    const int bm = blockIdx.y * 128;
    const int bn = blockIdx.x * 128;
    if (CAUSAL_SKIP && bn > bm) return;   // fully-masked tile

    const int z = blockIdx.z;
    A += (long)z * sA;
    B += (long)(z / bdiv) * sB;
    C += (long)z * sC;

    __shared__ unsigned As[32][136];   // [k][m], pad 8 -> conflict-free frag loads
    __shared__ unsigned Bs[32][136];   // [k][n]

    const int tid  = threadIdx.x;       // 256 threads = 8 warps
    const int lane = tid & 31;
    const int wid  = tid >> 5;
    const int wm   = wid & 3;           // warp row: 4 x 32 rows
    const int wn   = wid >> 2;          // warp col: 2 x 64 cols
    const int gid  = lane >> 2;         // 0..7
    const int tig  = lane & 3;          // 0..3

    float acc[2][8][4];
    #pragma unroll
    for (int mt = 0; mt < 2; mt++)
        #pragma unroll
        for (int nt = 0; nt < 8; nt++)
            #pragma unroll
            for (int r = 0; r < 4; r++)
                acc[mt][nt][r] = 0.0f;

    const int kmax = CAUSAL_K ? min(K, bm + 128) : K;

    for (int k0 = 0; k0 < kmax; k0 += 32) {
        // ---- load A tile: 128 rows x 32 k (8 float4 per row) ----
        #pragma unroll
        for (int i = 0; i < 4; i++) {
            int f   = tid + i * 256;         // 0..1023
            int row = f >> 3;
            int c4  = f & 7;
            float4 v = *(const float4*)&A[(size_t)(bm + row) * lda + k0 + c4 * 4];
            As[c4 * 4 + 0][row] = f2tf32(v.x);
            As[c4 * 4 + 1][row] = f2tf32(v.y);
            As[c4 * 4 + 2][row] = f2tf32(v.z);
            As[c4 * 4 + 3][row] = f2tf32(v.w);
        }
        // ---- load B tile ----
        if (TB) {
            #pragma unroll
            for (int i = 0; i < 4; i++) {
                int f   = tid + i * 256;
                int row = f >> 3;            // n index
                int c4  = f & 7;
                float4 v = *(const float4*)&B[(size_t)(bn + row) * ldb + k0 + c4 * 4];
                Bs[c4 * 4 + 0][row] = f2tf32(v.x);
                Bs[c4 * 4 + 1][row] = f2tf32(v.y);
                Bs[c4 * 4 + 2][row] = f2tf32(v.z);
                Bs[c4 * 4 + 3][row] = f2tf32(v.w);
            }
        } else {
            #pragma unroll
            for (int i = 0; i < 4; i++) {
                int f  = tid + i * 256;
                int kk = f >> 5;             // 0..31
                int c4 = f & 31;             // 0..31
                float4 v = *(const float4*)&B[(size_t)(k0 + kk) * ldb + bn + c4 * 4];
                Bs[kk][c4 * 4 + 0] = f2tf32(v.x);
                Bs[kk][c4 * 4 + 1] = f2tf32(v.y);
                Bs[kk][c4 * 4 + 2] = f2tf32(v.z);
                Bs[kk][c4 * 4 + 3] = f2tf32(v.w);
            }
        }
        __syncthreads();

        // ---- compute: 4 k-steps of 8 ----
        #pragma unroll
        for (int ks = 0; ks < 32; ks += 8) {
            unsigned a[2][4];
            #pragma unroll
            for (int mt = 0; mt < 2; mt++) {
                int mrow = wm * 32 + mt * 16;
                a[mt][0] = As[ks + tig    ][mrow + gid];
                a[mt][1] = As[ks + tig    ][mrow + gid + 8];
                a[mt][2] = As[ks + tig + 4][mrow + gid];
                a[mt][3] = As[ks + tig + 4][mrow + gid + 8];
            }
            unsigned b[8][2];
            #pragma unroll
            for (int nt = 0; nt < 8; nt++) {
                int ncol = wn * 64 + nt * 8;
                b[nt][0] = Bs[ks + tig    ][ncol + gid];
                b[nt][1] = Bs[ks + tig + 4][ncol + gid];
            }
            #pragma unroll
            for (int mt = 0; mt < 2; mt++)
                #pragma unroll
                for (int nt = 0; nt < 8; nt++)
                    mma_tf32(acc[mt][nt],
                             a[mt][0], a[mt][1], a[mt][2], a[mt][3],
                             b[nt][0], b[nt][1]);
        }
        __syncthreads();
    }

    // ---- epilogue ----
    #pragma unroll
    for (int mt = 0; mt < 2; mt++) {
        #pragma unroll
        for (int nt = 0; nt < 8; nt++) {
            int r0 = bm + wm * 32 + mt * 16 + gid;
            int c0 = bn + wn * 64 + nt * 8 + tig * 2;
            float2 lo = make_float2(acc[mt][nt][0], acc[mt][nt][1]);
            float2 hi = make_float2(acc[mt][nt][2], acc[mt][nt][3]);
            *(float2*)&C[(size_t)r0       * ldc + c0] = lo;
            *(float2*)&C[(size_t)(r0 + 8) * ldc + c0] = hi;
        }
    }
}

// ---------------- RMSNorm + RoPE (in place) ----------------
__global__ void norm_rope_kernel(float* __restrict__ x,
                                 const float* __restrict__ w,
                                 const float* __restrict__ pcos,
                                 const float* __restrict__ psin,
                                 int rowstride)
{
    const int s = blockIdx.x;
    const int h = blockIdx.y;
    const int d = threadIdx.x;   // 0..127

    float* row = x + (size_t)s * rowstride + h * HD;
    float v = row[d];

    __shared__ float red[128];
    __shared__ float xsh[128];

    red[d] = v * v;
    __syncthreads();
    #pragma unroll
    for (int off = 64; off > 0; off >>= 1) {
        if (d < off) red[d] += red[d + off];
        __syncthreads();
    }
    float r = rsqrtf(red[0] * (1.0f / HD) + EPSV);
    float xn = v * r * w[d];
    xsh[d] = xn;
    __syncthreads();

    float c  = pcos[s * 64 + (d & 63)];
    float sn = psin[s * 64 + (d & 63)];
    float out;
    if (d < 64) out = xsh[d] * c - xsh[d + 64] * sn;
    else        out = xsh[d - 64] * sn + xsh[d] * c;
    row[d] = out;
}

// ---------------- softmax (scale + causal mask fused) ----------------
__global__ void softmax_kernel(float* __restrict__ scores)
{
    const int row = blockIdx.x;        // h*S + i
    const int i = row & (Sq - 1);
    float* p = scores + (size_t)row * Sq;
    const int t = threadIdx.x;

    float vals[8];
    float vmax = -INFINITY;
    #pragma unroll
    for (int j0 = 0; j0 < 8; j0++) {
        int j = t + j0 * 256;
        float v = p[j] * SCALEV + (j <= i ? 0.0f : NEGV);
        vals[j0] = v;
        vmax = fmaxf(vmax, v);
    }

    __shared__ float sh[256];
    sh[t] = vmax;
    __syncthreads();
    #pragma unroll
    for (int off = 128; off > 0; off >>= 1) {
        if (t < off) sh[t] = fmaxf(sh[t], sh[t + off]);
        __syncthreads();
    }
    vmax = sh[0];
    __syncthreads();

    float sum = 0.0f;
    #pragma unroll
    for (int j0 = 0; j0 < 8; j0++) {
        vals[j0] = __expf(vals[j0] - vmax);
        sum += vals[j0];
    }
    sh[t] = sum;
    __syncthreads();
    #pragma unroll
    for (int off = 128; off > 0; off >>= 1) {
        if (t < off) sh[t] += sh[t + off];
        __syncthreads();
    }
    float inv = 1.0f / sh[0];
    #pragma unroll
    for (int j0 = 0; j0 < 8; j0++)
        p[t + j0 * 256] = vals[j0] * inv;
}

// ---------------- k_new / v_new tail copy ----------------
__global__ void tail_copy_kernel(const float* __restrict__ k,
                                 const float* __restrict__ v,
                                 float* __restrict__ out)
{
    int t = blockIdx.x * blockDim.x + threadIdx.x;   // 0..2047
    const size_t base = (size_t)Sq * HIDN;           // after y
    if (t < NKH * HD)
        out[base + t] = k[(size_t)(Sq - 1) * (NKH * HD) + t];
    else
        out[base + t] = v[(size_t)(Sq - 1) * (NKH * HD) + (t - NKH * HD)];
}

// ---------------- launcher ----------------
extern "C" void kernel_launch(void* const* d_in, const int* in_sizes, int n_in,
                              void* d_out, int out_size)
{
    const float* hs   = (const float*)d_in[0];
    const float* pcos = (const float*)d_in[1];
    const float* psin = (const float*)d_in[2];
    // d_in[3] = atten_mask (causal, reproduced arithmetically)
    const float* Wq   = (const float*)d_in[4];
    const float* Wk   = (const float*)d_in[5];
    const float* Wv   = (const float*)d_in[6];
    const float* Wo   = (const float*)d_in[7];
    const float* qw   = (const float*)d_in[8];
    const float* kw   = (const float*)d_in[9];
    float* out = (float*)d_out;

    float *q, *k, *v, *sc, *y;
    cudaGetSymbolAddress((void**)&q,  g_q);
    cudaGetSymbolAddress((void**)&k,  g_k);
    cudaGetSymbolAddress((void**)&v,  g_v);
    cudaGetSymbolAddress((void**)&sc, g_scores);
    cudaGetSymbolAddress((void**)&y,  g_y);

    dim3 blk(256);

    // ---- QKV projections: X(2048x2048) @ W^T ----
    mma_gemm<true, false, false><<<dim3(16, 16, 1), blk>>>(
        hs, Wq, q, Sq, NH * HD, HIDN, HIDN, HIDN, NH * HD, 0, 0, 0, 1);
    mma_gemm<true, false, false><<<dim3(8, 16, 1), blk>>>(
        hs, Wk, k, Sq, NKH * HD, HIDN, HIDN, HIDN, NKH * HD, 0, 0, 0, 1);
    mma_gemm<true, false, false><<<dim3(8, 16, 1), blk>>>(
        hs, Wv, v, Sq, NKH * HD, HIDN, HIDN, HIDN, NKH * HD, 0, 0, 0, 1);

    // ---- RMSNorm + RoPE ----
    norm_rope_kernel<<<dim3(Sq, NH),  128>>>(q, qw, pcos, psin, NH * HD);
    norm_rope_kernel<<<dim3(Sq, NKH), 128>>>(k, kw, pcos, psin, NKH * HD);

    // ---- scores (batched over heads, lower-triangle blocks only) ----
    mma_gemm<true, true, false><<<dim3(16, 16, NH), blk>>>(
        q, k, sc, Sq, Sq, HD, NH * HD, NKH * HD, Sq,
        (long)HD, (long)HD, (long)Sq * Sq, GRP);

    // ---- softmax with scale + causal mask ----
    softmax_kernel<<<NH * Sq, 256>>>(sc);

    // ---- AV (batched over heads, K clamped to causal extent) ----
    mma_gemm<false, false, true><<<dim3(1, 16, NH), blk>>>(
        sc, v, y, Sq, HD, Sq, Sq, NKH * HD, NH * HD,
        (long)Sq * Sq, (long)HD, (long)HD, GRP);

    // ---- output projection: Y(2048x2048) @ Wo^T ----
    mma_gemm<true, false, false><<<dim3(16, 16, 1), blk>>>(
        y, Wo, out, Sq, HIDN, HIDN, NH * HD, HIDN, HIDN, 0, 0, 0, 1);

    // ---- k_new / v_new ----
    tail_copy_kernel<<<8, 256>>>(k, v, out);
}

// round 3
// speedup vs baseline: 9.8832x; 1.2437x over previous
#include <cuda_runtime.h>
#include <cuda_bf16.h>
#include <math.h>

// Problem constants
#define Sq    2048
#define HIDN  2048
#define NH    16
#define NKH   8
#define HD    128
#define GRP   2          // NH / NKH
#define EPSV  1e-6f
#define SCALEV 0.08838834764831845f   // 128^-0.5

// ---------------- static device scratch (allocation-free rule) ----------------
__device__ float g_q[Sq * NH * HD];               // 2048 x 2048
__device__ float g_k[Sq * NKH * HD];              // 2048 x 1024
__device__ float g_v[Sq * NKH * HD];              // 2048 x 1024
__device__ float g_y[Sq * NH * HD];               // 2048 x 2048

// ---------------- tf32 helpers ----------------
__device__ __forceinline__ unsigned f2tf32(float f) {
    unsigned u;
    asm("cvt.rna.tf32.f32 %0, %1;" : "=r"(u) : "f"(f));
    return u;
}

__device__ __forceinline__ void mma_tf32(float c[4],
                                         unsigned a0, unsigned a1, unsigned a2, unsigned a3,
                                         unsigned b0, unsigned b1)
{
    asm volatile(
        "mma.sync.aligned.m16n8k8.row.col.f32.tf32.tf32.f32 "
        "{%0,%1,%2,%3}, {%4,%5,%6,%7}, {%8,%9}, {%0,%1,%2,%3};"
        : "+f"(c[0]), "+f"(c[1]), "+f"(c[2]), "+f"(c[3])
        : "r"(a0), "r"(a1), "r"(a2), "r"(a3), "r"(b0), "r"(b1));
}

// ---------------- tf32 tensor-core GEMM (projections) ----------------
template <bool TB>
__global__ __launch_bounds__(256)
void mma_gemm(const float* __restrict__ A,
              const float* __restrict__ B,
              float* __restrict__ C,
              int M, int N, int K,
              int lda, int ldb, int ldc)
{
    const int bm = blockIdx.y * 128;
    const int bn = blockIdx.x * 128;

    __shared__ unsigned As[32][136];   // [k][m]
    __shared__ unsigned Bs[32][136];   // [k][n]

    const int tid  = threadIdx.x;       // 256 threads = 8 warps
    const int lane = tid & 31;
    const int wid  = tid >> 5;
    const int wm   = wid & 3;           // 4 x 32 rows
    const int wn   = wid >> 2;          // 2 x 64 cols
    const int gid  = lane >> 2;
    const int tig  = lane & 3;

    float acc[2][8][4];
    #pragma unroll
    for (int mt = 0; mt < 2; mt++)
        #pragma unroll
        for (int nt = 0; nt < 8; nt++)
            #pragma unroll
            for (int r = 0; r < 4; r++)
                acc[mt][nt][r] = 0.0f;

    for (int k0 = 0; k0 < K; k0 += 32) {
        #pragma unroll
        for (int i = 0; i < 4; i++) {
            int f   = tid + i * 256;
            int row = f >> 3;
            int c4  = f & 7;
            float4 v = *(const float4*)&A[(size_t)(bm + row) * lda + k0 + c4 * 4];
            As[c4 * 4 + 0][row] = f2tf32(v.x);
            As[c4 * 4 + 1][row] = f2tf32(v.y);
            As[c4 * 4 + 2][row] = f2tf32(v.z);
            As[c4 * 4 + 3][row] = f2tf32(v.w);
        }
        if (TB) {
            #pragma unroll
            for (int i = 0; i < 4; i++) {
                int f   = tid + i * 256;
                int row = f >> 3;
                int c4  = f & 7;
                float4 v = *(const float4*)&B[(size_t)(bn + row) * ldb + k0 + c4 * 4];
                Bs[c4 * 4 + 0][row] = f2tf32(v.x);
                Bs[c4 * 4 + 1][row] = f2tf32(v.y);
                Bs[c4 * 4 + 2][row] = f2tf32(v.z);
                Bs[c4 * 4 + 3][row] = f2tf32(v.w);
            }
        } else {
            #pragma unroll
            for (int i = 0; i < 4; i++) {
                int f  = tid + i * 256;
                int kk = f >> 5;
                int c4 = f & 31;
                float4 v = *(const float4*)&B[(size_t)(k0 + kk) * ldb + bn + c4 * 4];
                Bs[kk][c4 * 4 + 0] = f2tf32(v.x);
                Bs[kk][c4 * 4 + 1] = f2tf32(v.y);
                Bs[kk][c4 * 4 + 2] = f2tf32(v.z);
                Bs[kk][c4 * 4 + 3] = f2tf32(v.w);
            }
        }
        __syncthreads();

        #pragma unroll
        for (int ks = 0; ks < 32; ks += 8) {
            unsigned a[2][4];
            #pragma unroll
            for (int mt = 0; mt < 2; mt++) {
                int mrow = wm * 32 + mt * 16;
                a[mt][0] = As[ks + tig    ][mrow + gid];
                a[mt][1] = As[ks + tig    ][mrow + gid + 8];
                a[mt][2] = As[ks + tig + 4][mrow + gid];
                a[mt][3] = As[ks + tig + 4][mrow + gid + 8];
            }
            unsigned b[8][2];
            #pragma unroll
            for (int nt = 0; nt < 8; nt++) {
                int ncol = wn * 64 + nt * 8;
                b[nt][0] = Bs[ks + tig    ][ncol + gid];
                b[nt][1] = Bs[ks + tig + 4][ncol + gid];
            }
            #pragma unroll
            for (int mt = 0; mt < 2; mt++)
                #pragma unroll
                for (int nt = 0; nt < 8; nt++)
                    mma_tf32(acc[mt][nt],
                             a[mt][0], a[mt][1], a[mt][2], a[mt][3],
                             b[nt][0], b[nt][1]);
        }
        __syncthreads();
    }

    #pragma unroll
    for (int mt = 0; mt < 2; mt++) {
        #pragma unroll
        for (int nt = 0; nt < 8; nt++) {
            int r0 = bm + wm * 32 + mt * 16 + gid;
            int c0 = bn + wn * 64 + nt * 8 + tig * 2;
            *(float2*)&C[(size_t)r0       * ldc + c0] = make_float2(acc[mt][nt][0], acc[mt][nt][1]);
            *(float2*)&C[(size_t)(r0 + 8) * ldc + c0] = make_float2(acc[mt][nt][2], acc[mt][nt][3]);
        }
    }
}

// ---------------- fused flash attention (tf32 mma, online softmax) ----------------
// grid (NH, Sq/128), block 256 (8 warps; warp w owns rows w*16..w*16+15)
// smem: Qs[128][132], Ks[64][132], Vs[64][136] (tf32-as-uint, padded row-major)
#define QS_PAD 132
#define KS_PAD 132
#define VS_PAD 136
#define SM_QS  0
#define SM_KS  (128 * QS_PAD)
#define SM_VS  (SM_KS + 64 * KS_PAD)
#define SM_TOT ((SM_VS + 64 * VS_PAD) * 4)   // bytes = 136192

__global__ __launch_bounds__(256, 1)
void flash_kernel(const float* __restrict__ q,
                  const float* __restrict__ k,
                  const float* __restrict__ v,
                  float* __restrict__ y)
{
    extern __shared__ unsigned sm[];
    unsigned* Qs = sm + SM_QS;
    unsigned* Ks = sm + SM_KS;
    unsigned* Vs = sm + SM_VS;

    const int head = blockIdx.x;
    const int kh   = head / GRP;
    const int bq   = (gridDim.y - 1) - blockIdx.y;   // heavy blocks first

    const int tid  = threadIdx.x;
    const int lane = tid & 31;
    const int wid  = tid >> 5;
    const int gid  = lane >> 2;
    const int tig  = lane & 3;

    // ---- load Q tile (128 x 128) ----
    #pragma unroll
    for (int i = 0; i < 16; i++) {
        int f   = tid + i * 256;
        int row = f >> 5;
        int c4  = f & 31;
        float4 t = *(const float4*)&q[(size_t)(bq * 128 + row) * (NH * HD) + head * HD + c4 * 4];
        *(uint4*)&Qs[row * QS_PAD + c4 * 4] =
            make_uint4(f2tf32(t.x), f2tf32(t.y), f2tf32(t.z), f2tf32(t.w));
    }

    float Oa[16][4];
    #pragma unroll
    for (int nt = 0; nt < 16; nt++)
        #pragma unroll
        for (int r = 0; r < 4; r++)
            Oa[nt][r] = 0.0f;
    float mrow0 = -1e30f, mrow1 = -1e30f;
    float lrow0 = 0.0f,   lrow1 = 0.0f;

    const int i0 = bq * 128 + wid * 16 + gid;   // this thread's row (and +8)
    const int nkb = 2 * (bq + 1);

    for (int kb = 0; kb < nkb; kb++) {
        const int k0 = kb * 64;

        __syncthreads();   // previous iteration's reads done before overwrite
        // ---- load K,V tiles (64 x 128 each) ----
        #pragma unroll
        for (int i = 0; i < 8; i++) {
            int f   = tid + i * 256;
            int key = f >> 5;
            int c4  = f & 31;
            size_t goff = (size_t)(k0 + key) * (NKH * HD) + kh * HD + c4 * 4;
            float4 tk = *(const float4*)&k[goff];
            *(uint4*)&Ks[key * KS_PAD + c4 * 4] =
                make_uint4(f2tf32(tk.x), f2tf32(tk.y), f2tf32(tk.z), f2tf32(tk.w));
            float4 tv = *(const float4*)&v[goff];
            *(uint4*)&Vs[key * VS_PAD + c4 * 4] =
                make_uint4(f2tf32(tv.x), f2tf32(tv.y), f2tf32(tv.z), f2tf32(tv.w));
        }
        __syncthreads();

        // ---- S = Q @ K^T : per-warp 16 x 64 ----
        float s[8][4];
        #pragma unroll
        for (int nt = 0; nt < 8; nt++)
            #pragma unroll
            for (int r = 0; r < 4; r++)
                s[nt][r] = 0.0f;

        #pragma unroll
        for (int ks = 0; ks < 128; ks += 8) {
            unsigned a0 = Qs[(wid * 16 + gid    ) * QS_PAD + ks + tig];
            unsigned a1 = Qs[(wid * 16 + gid + 8) * QS_PAD + ks + tig];
            unsigned a2 = Qs[(wid * 16 + gid    ) * QS_PAD + ks + tig + 4];
            unsigned a3 = Qs[(wid * 16 + gid + 8) * QS_PAD + ks + tig + 4];
            #pragma unroll
            for (int nt = 0; nt < 8; nt++) {
                unsigned b0 = Ks[(nt * 8 + gid) * KS_PAD + ks + tig];
                unsigned b1 = Ks[(nt * 8 + gid) * KS_PAD + ks + tig + 4];
                mma_tf32(s[nt], a0, a1, a2, a3, b0, b1);
            }
        }

        // ---- scale + causal mask ----
        const bool diag = (k0 + 64 > bq * 128);   // tile may need masking
        #pragma unroll
        for (int nt = 0; nt < 8; nt++) {
            int j = k0 + nt * 8 + tig * 2;
            #pragma unroll
            for (int r = 0; r < 4; r++) {
                int jj = j + (r & 1);
                int ii = i0 + ((r >> 1) << 3);
                float val = s[nt][r] * SCALEV;
                if (diag && jj > ii) val = -1e30f;
                s[nt][r] = val;
            }
        }

        // ---- online softmax update ----
        float mx0 = -1e30f, mx1 = -1e30f;
        #pragma unroll
        for (int nt = 0; nt < 8; nt++) {
            mx0 = fmaxf(mx0, fmaxf(s[nt][0], s[nt][1]));
            mx1 = fmaxf(mx1, fmaxf(s[nt][2], s[nt][3]));
        }
        mx0 = fmaxf(mx0, __shfl_xor_sync(0xffffffffu, mx0, 1));
        mx0 = fmaxf(mx0, __shfl_xor_sync(0xffffffffu, mx0, 2));
        mx1 = fmaxf(mx1, __shfl_xor_sync(0xffffffffu, mx1, 1));
        mx1 = fmaxf(mx1, __shfl_xor_sync(0xffffffffu, mx1, 2));

        float mnew0 = fmaxf(mrow0, mx0);
        float mnew1 = fmaxf(mrow1, mx1);
        float corr0 = __expf(mrow0 - mnew0);
        float corr1 = __expf(mrow1 - mnew1);
        mrow0 = mnew0; mrow1 = mnew1;

        float sum0 = 0.0f, sum1 = 0.0f;
        #pragma unroll
        for (int nt = 0; nt < 8; nt++) {
            s[nt][0] = __expf(s[nt][0] - mnew0);
            s[nt][1] = __expf(s[nt][1] - mnew0);
            s[nt][2] = __expf(s[nt][2] - mnew1);
            s[nt][3] = __expf(s[nt][3] - mnew1);
            sum0 += s[nt][0] + s[nt][1];
            sum1 += s[nt][2] + s[nt][3];
        }
        sum0 += __shfl_xor_sync(0xffffffffu, sum0, 1);
        sum0 += __shfl_xor_sync(0xffffffffu, sum0, 2);
        sum1 += __shfl_xor_sync(0xffffffffu, sum1, 1);
        sum1 += __shfl_xor_sync(0xffffffffu, sum1, 2);
        lrow0 = lrow0 * corr0 + sum0;
        lrow1 = lrow1 * corr1 + sum1;

        #pragma unroll
        for (int nt = 0; nt < 16; nt++) {
            Oa[nt][0] *= corr0;  Oa[nt][1] *= corr0;
            Oa[nt][2] *= corr1;  Oa[nt][3] *= corr1;
        }

        // ---- O += P @ V : A-frags from s via quad shuffles ----
        const int srcA = (lane & ~3) | (tig >> 1);
        const int srcB = srcA + 2;
        const bool odd = (tig & 1);
        #pragma unroll
        for (int ks8 = 0; ks8 < 8; ks8++) {
            unsigned p0 = f2tf32(s[ks8][0]);
            unsigned p1 = f2tf32(s[ks8][1]);
            unsigned p2 = f2tf32(s[ks8][2]);
            unsigned p3 = f2tf32(s[ks8][3]);
            unsigned x0 = __shfl_sync(0xffffffffu, p0, srcA);
            unsigned x1 = __shfl_sync(0xffffffffu, p1, srcA);
            unsigned x2 = __shfl_sync(0xffffffffu, p2, srcA);
            unsigned x3 = __shfl_sync(0xffffffffu, p3, srcA);
            unsigned y0 = __shfl_sync(0xffffffffu, p0, srcB);
            unsigned y1 = __shfl_sync(0xffffffffu, p1, srcB);
            unsigned y2 = __shfl_sync(0xffffffffu, p2, srcB);
            unsigned y3 = __shfl_sync(0xffffffffu, p3, srcB);
            unsigned a0 = odd ? x1 : x0;
            unsigned a1 = odd ? x3 : x2;
            unsigned a2 = odd ? y1 : y0;
            unsigned a3 = odd ? y3 : y2;
            #pragma unroll
            for (int nt = 0; nt < 16; nt++) {
                unsigned b0 = Vs[(ks8 * 8 + tig    ) * VS_PAD + nt * 8 + gid];
                unsigned b1 = Vs[(ks8 * 8 + tig + 4) * VS_PAD + nt * 8 + gid];
                mma_tf32(Oa[nt], a0, a1, a2, a3, b0, b1);
            }
        }
    }

    // ---- finalize & store ----
    float inv0 = 1.0f / lrow0;
    float inv1 = 1.0f / lrow1;
    #pragma unroll
    for (int nt = 0; nt < 16; nt++) {
        int c0 = head * HD + nt * 8 + tig * 2;
        *(float2*)&y[(size_t)i0       * (NH * HD) + c0] = make_float2(Oa[nt][0] * inv0, Oa[nt][1] * inv0);
        *(float2*)&y[(size_t)(i0 + 8) * (NH * HD) + c0] = make_float2(Oa[nt][2] * inv1, Oa[nt][3] * inv1);
    }
}

// ---------------- RMSNorm + RoPE (in place) ----------------
__global__ void norm_rope_kernel(float* __restrict__ x,
                                 const float* __restrict__ w,
                                 const float* __restrict__ pcos,
                                 const float* __restrict__ psin,
                                 int rowstride)
{
    const int s = blockIdx.x;
    const int h = blockIdx.y;
    const int d = threadIdx.x;   // 0..127

    float* row = x + (size_t)s * rowstride + h * HD;
    float v = row[d];

    __shared__ float red[128];
    __shared__ float xsh[128];

    red[d] = v * v;
    __syncthreads();
    #pragma unroll
    for (int off = 64; off > 0; off >>= 1) {
        if (d < off) red[d] += red[d + off];
        __syncthreads();
    }
    float r = rsqrtf(red[0] * (1.0f / HD) + EPSV);
    float xn = v * r * w[d];
    xsh[d] = xn;
    __syncthreads();

    float c  = pcos[s * 64 + (d & 63)];
    float sn = psin[s * 64 + (d & 63)];
    float out;
    if (d < 64) out = xsh[d] * c - xsh[d + 64] * sn;
    else        out = xsh[d - 64] * sn + xsh[d] * c;
    row[d] = out;
}

// ---------------- k_new / v_new tail copy ----------------
__global__ void tail_copy_kernel(const float* __restrict__ k,
                                 const float* __restrict__ v,
                                 float* __restrict__ out)
{
    int t = blockIdx.x * blockDim.x + threadIdx.x;   // 0..2047
    const size_t base = (size_t)Sq * HIDN;           // after y
    if (t < NKH * HD)
        out[base + t] = k[(size_t)(Sq - 1) * (NKH * HD) + t];
    else
        out[base + t] = v[(size_t)(Sq - 1) * (NKH * HD) + (t - NKH * HD)];
}

// ---------------- launcher ----------------
extern "C" void kernel_launch(void* const* d_in, const int* in_sizes, int n_in,
                              void* d_out, int out_size)
{
    const float* hs   = (const float*)d_in[0];
    const float* pcos = (const float*)d_in[1];
    const float* psin = (const float*)d_in[2];
    // d_in[3] = atten_mask (causal, reproduced arithmetically)
    const float* Wq   = (const float*)d_in[4];
    const float* Wk   = (const float*)d_in[5];
    const float* Wv   = (const float*)d_in[6];
    const float* Wo   = (const float*)d_in[7];
    const float* qw   = (const float*)d_in[8];
    const float* kw   = (const float*)d_in[9];
    float* out = (float*)d_out;

    float *q, *k, *v, *y;
    cudaGetSymbolAddress((void**)&q, g_q);
    cudaGetSymbolAddress((void**)&k, g_k);
    cudaGetSymbolAddress((void**)&v, g_v);
    cudaGetSymbolAddress((void**)&y, g_y);

    cudaFuncSetAttribute(flash_kernel,
                         cudaFuncAttributeMaxDynamicSharedMemorySize, SM_TOT);

    dim3 blk(256);

    // ---- QKV projections: X(2048x2048) @ W^T ----
    mma_gemm<true><<<dim3(16, 16), blk>>>(hs, Wq, q, Sq, NH * HD,  HIDN, HIDN, HIDN, NH * HD);
    mma_gemm<true><<<dim3(8,  16), blk>>>(hs, Wk, k, Sq, NKH * HD, HIDN, HIDN, HIDN, NKH * HD);
    mma_gemm<true><<<dim3(8,  16), blk>>>(hs, Wv, v, Sq, NKH * HD, HIDN, HIDN, HIDN, NKH * HD);

    // ---- RMSNorm + RoPE ----
    norm_rope_kernel<<<dim3(Sq, NH),  128>>>(q, qw, pcos, psin, NH * HD);
    norm_rope_kernel<<<dim3(Sq, NKH), 128>>>(k, kw, pcos, psin, NKH * HD);

    // ---- fused attention (scores + softmax + AV) ----
    flash_kernel<<<dim3(NH, Sq / 128), blk, SM_TOT>>>(q, k, v, y);

    // ---- output projection: Y(2048x2048) @ Wo^T ----
    mma_gemm<true><<<dim3(16, 16), blk>>>(y, Wo, out, Sq, HIDN, HIDN, NH * HD, HIDN, HIDN);

    // ---- k_new / v_new ----
    tail_copy_kernel<<<8, 256>>>(k, v, out);
}